// round 2
// baseline (speedup 1.0000x reference)
#include <cuda_runtime.h>

#define T_STEPS 2048
#define HID 64

typedef unsigned long long u64;

// ---------- f32x2 packed math (sm_103a FFMA2 path; 2 MAC per FMA-pipe issue) ----------
__device__ __forceinline__ u64 fma2(u64 a, u64 b, u64 c) {
    u64 d; asm("fma.rn.f32x2 %0, %1, %2, %3;" : "=l"(d) : "l"(a), "l"(b), "l"(c)); return d;
}
__device__ __forceinline__ u64 add2(u64 a, u64 b) {
    u64 d; asm("add.rn.f32x2 %0, %1, %2;" : "=l"(d) : "l"(a), "l"(b)); return d;
}
__device__ __forceinline__ u64 dup2(float x) {
    u64 d; asm("mov.b64 %0, {%1, %1};" : "=l"(d) : "f"(x)); return d;
}
__device__ __forceinline__ u64 pack2(float lo, float hi) {
    u64 d; asm("mov.b64 %0, {%1, %2};" : "=l"(d) : "f"(lo), "f"(hi)); return d;
}
__device__ __forceinline__ float2 unpack2(u64 v) {
    float lo, hi; asm("mov.b64 {%0, %1}, %2;" : "=f"(lo), "=f"(hi) : "l"(v));
    return make_float2(lo, hi);
}

// ---------- activations (MUFU-based, ~1e-6 rel err; safe at saturation) ----------
__device__ __forceinline__ float sigmoid_(float x) {
    return __fdividef(1.0f, 1.0f + __expf(-x));
}
__device__ __forceinline__ float tanh_(float x) {
    float e = __expf(2.0f * fabsf(x));          // -> inf for large |x|, handled below
    float t = 1.0f - __fdividef(2.0f, e + 1.0f); // -> 1
    return copysignf(t, x);
}

// 512 MB scratch for layer-0 hidden states (allowed: __device__ global array)
__device__ float g_h1[(size_t)1024 * T_STEPS * HID];

// =====================================================================================
// Kernel 1: layer-0 LSTM. One block per batch element. 256 thr = 64 gate-quads x 4 k-splits.
// Thread (t,s): gates {i_t, f_t, g_t, o_t}, k in [16s, 16s+16). Weights in registers as f32x2.
// =====================================================================================
__global__ __launch_bounds__(256, 2)
void lstm_layer0(const float* __restrict__ x, const float* __restrict__ Wih0,
                 const float* __restrict__ Whh0, const float* __restrict__ bih0,
                 const float* __restrict__ bhh0)
{
    __shared__ float x_sh[T_STEPS];           // 8 KB: this element's full input row
    __shared__ float h_sh[2][HID];            // double-buffered hidden state
    __shared__ ulonglong2 psh[3][HID];        // split-k partials (s=1..3)

    const int tid = threadIdx.x;
    const int t = tid & 63;
    const int s = tid >> 6;
    const int b = blockIdx.x;

    // stage input row into SMEM (coalesced float4)
    {
        const float4* xg = (const float4*)(x + (size_t)b * T_STEPS);
        float4* xs = (float4*)x_sh;
        for (int i = tid; i < T_STEPS / 4; i += 256) xs[i] = xg[i];
    }

    // register-resident recurrent weights: pairs (W_i,W_f) and (W_g,W_o) per k
    u64 wif[16], wgo[16];
    const int ri = t, rf = 64 + t, rg = 128 + t, ro = 192 + t;
#pragma unroll
    for (int j = 0; j < 16; ++j) {
        int k = s * 16 + j;
        wif[j] = pack2(Whh0[ri * 64 + k], Whh0[rf * 64 + k]);
        wgo[j] = pack2(Whh0[rg * 64 + k], Whh0[ro * 64 + k]);
    }
    u64 xwif = 0, xwgo = 0, bif = 0, bgo = 0;
    float c = 0.0f;
    if (s == 0) {
        xwif = pack2(Wih0[ri], Wih0[rf]);
        xwgo = pack2(Wih0[rg], Wih0[ro]);
        bif = pack2(bih0[ri] + bhh0[ri], bih0[rf] + bhh0[rf]);
        bgo = pack2(bih0[rg] + bhh0[rg], bih0[ro] + bhh0[ro]);
        h_sh[0][t] = 0.0f;   // h0 = 0
    }
    __syncthreads();

    float* outp = g_h1 + ((size_t)b * T_STEPS) * HID + t;

#pragma unroll 1
    for (int step = 0; step < T_STEPS; ++step) {
        const int cur = step & 1;
        u64 aif, ago;
        if (s == 0) {
            u64 x2 = dup2(x_sh[step]);
            aif = fma2(x2, xwif, bif);
            ago = fma2(x2, xwgo, bgo);
        } else { aif = 0ULL; ago = 0ULL; }

        const float4* hp = (const float4*)&h_sh[cur][s * 16];   // warp-uniform -> LDS broadcast
#pragma unroll
        for (int j = 0; j < 4; ++j) {
            float4 h4 = hp[j];
            u64 d0 = dup2(h4.x), d1 = dup2(h4.y), d2 = dup2(h4.z), d3 = dup2(h4.w);
            aif = fma2(d0, wif[4 * j + 0], aif); ago = fma2(d0, wgo[4 * j + 0], ago);
            aif = fma2(d1, wif[4 * j + 1], aif); ago = fma2(d1, wgo[4 * j + 1], ago);
            aif = fma2(d2, wif[4 * j + 2], aif); ago = fma2(d2, wgo[4 * j + 2], ago);
            aif = fma2(d3, wif[4 * j + 3], aif); ago = fma2(d3, wgo[4 * j + 3], ago);
        }
        if (s > 0) psh[s - 1][t] = make_ulonglong2(aif, ago);
        __syncthreads();
        if (s == 0) {
#pragma unroll
            for (int p = 0; p < 3; ++p) {
                ulonglong2 v = psh[p][t];
                aif = add2(aif, v.x); ago = add2(ago, v.y);
            }
            float2 sif = unpack2(aif), sgo = unpack2(ago);
            float ig = sigmoid_(sif.x), fg = sigmoid_(sif.y);
            float gg = tanh_(sgo.x),    og = sigmoid_(sgo.y);
            c = fg * c + ig * gg;
            float h = og * tanh_(c);
            h_sh[cur ^ 1][t] = h;
            outp[(size_t)step * HID] = h;
        }
        __syncthreads();
    }
}

// =====================================================================================
// Kernel 2: layer-1 LSTM + final FC. One block per batch element. 256 thr = 64 x 4 splits,
// K=128 (64 from h1 scratch + 64 recurrent). h1 streamed in 16-step / 4KB chunks,
// double-buffered with register prefetch.
// =====================================================================================
__global__ __launch_bounds__(256, 1)
void lstm_layer1_fc(const float* __restrict__ Wih1, const float* __restrict__ Whh1,
                    const float* __restrict__ bih1, const float* __restrict__ bhh1,
                    const float* __restrict__ fcW, const float* __restrict__ fcb,
                    float* __restrict__ out)
{
    __shared__ float sh1[2][16 * HID];        // h1 chunk double buffer (2 x 4KB)
    __shared__ float h2_sh[2][HID];           // layer-1 hidden state
    __shared__ ulonglong2 psh[3][HID];

    const int tid = threadIdx.x;
    const int t = tid & 63;
    const int s = tid >> 6;
    const int b = blockIdx.x;

    // combined [Wih1 | Whh1] rows, k in [32s, 32s+32), as f32x2 pairs: 128 regs
    u64 wif[32], wgo[32];
    const int ri = t, rf = 64 + t, rg = 128 + t, ro = 192 + t;
#pragma unroll
    for (int j = 0; j < 32; ++j) {
        int k = s * 32 + j;
        if (k < 64) {
            wif[j] = pack2(Wih1[ri * 64 + k], Wih1[rf * 64 + k]);
            wgo[j] = pack2(Wih1[rg * 64 + k], Wih1[ro * 64 + k]);
        } else {
            int k2 = k - 64;
            wif[j] = pack2(Whh1[ri * 64 + k2], Whh1[rf * 64 + k2]);
            wgo[j] = pack2(Whh1[rg * 64 + k2], Whh1[ro * 64 + k2]);
        }
    }
    u64 bif = 0, bgo = 0;
    float c = 0.0f;
    if (s == 0) {
        bif = pack2(bih1[ri] + bhh1[ri], bih1[rf] + bhh1[rf]);
        bgo = pack2(bih1[rg] + bhh1[rg], bih1[ro] + bhh1[ro]);
        h2_sh[0][t] = 0.0f;  // h0 = 0
    }

    const float* h1base = g_h1 + (size_t)b * T_STEPS * HID;
    // prologue: chunk 0 -> sh1[0]; prefetch chunk 1 into registers
    float4 v0 = ((const float4*)h1base)[tid];
    ((float4*)sh1[0])[tid] = v0;
    float4 pf = ((const float4*)h1base)[256 + tid];
    __syncthreads();

#pragma unroll 1
    for (int step = 0; step < T_STEPS; ++step) {
        const int grp = step >> 4;
        const int phase = step & 15;
        const int cbuf = grp & 1;
        const int cur = step & 1;

        u64 aif, ago;
        if (s == 0) { aif = bif; ago = bgo; } else { aif = 0ULL; ago = 0ULL; }

        const float4* vp = (s < 2)
            ? (const float4*)&sh1[cbuf][phase * HID + s * 32]
            : (const float4*)&h2_sh[cur][(s - 2) * 32];
#pragma unroll
        for (int j = 0; j < 8; ++j) {
            float4 h4 = vp[j];
            u64 d0 = dup2(h4.x), d1 = dup2(h4.y), d2 = dup2(h4.z), d3 = dup2(h4.w);
            aif = fma2(d0, wif[4 * j + 0], aif); ago = fma2(d0, wgo[4 * j + 0], ago);
            aif = fma2(d1, wif[4 * j + 1], aif); ago = fma2(d1, wgo[4 * j + 1], ago);
            aif = fma2(d2, wif[4 * j + 2], aif); ago = fma2(d2, wgo[4 * j + 2], ago);
            aif = fma2(d3, wif[4 * j + 3], aif); ago = fma2(d3, wgo[4 * j + 3], ago);
        }
        if (s > 0) psh[s - 1][t] = make_ulonglong2(aif, ago);
        __syncthreads();
        if (s == 0) {
#pragma unroll
            for (int p = 0; p < 3; ++p) {
                ulonglong2 v = psh[p][t];
                aif = add2(aif, v.x); ago = add2(ago, v.y);
            }
            float2 sif = unpack2(aif), sgo = unpack2(ago);
            float ig = sigmoid_(sif.x), fg = sigmoid_(sif.y);
            float gg = tanh_(sgo.x),    og = sigmoid_(sgo.y);
            c = fg * c + ig * gg;
            float h = og * tanh_(c);
            h2_sh[cur ^ 1][t] = h;
        }
        if (phase == 15) {
            // publish prefetched next chunk, kick prefetch for the one after
            ((float4*)sh1[cbuf ^ 1])[tid] = pf;
            int nc = grp + 2;
            if (nc < T_STEPS / 16) pf = ((const float4*)h1base)[nc * 256 + tid];
        }
        __syncthreads();
    }

    // final FC: logits[b] = h2_last . fcW + fcb   (h2_last lives in h2_sh[0])
    if (tid == 0) {
        float acc = fcb[0];
#pragma unroll
        for (int k = 0; k < HID; ++k) acc += h2_sh[0][k] * fcW[k];
        out[b] = acc;
    }
}

extern "C" void kernel_launch(void* const* d_in, const int* in_sizes, int n_in,
                              void* d_out, int out_size)
{
    const float* x    = (const float*)d_in[0];
    const float* Wih0 = (const float*)d_in[1];
    const float* Whh0 = (const float*)d_in[2];
    const float* bih0 = (const float*)d_in[3];
    const float* bhh0 = (const float*)d_in[4];
    const float* Wih1 = (const float*)d_in[5];
    const float* Whh1 = (const float*)d_in[6];
    const float* bih1 = (const float*)d_in[7];
    const float* bhh1 = (const float*)d_in[8];
    const float* fcW  = (const float*)d_in[9];
    const float* fcb  = (const float*)d_in[10];
    float* out = (float*)d_out;

    int B = in_sizes[0] / T_STEPS;
    if (B > 1024) B = 1024;   // scratch sized for B=1024

    lstm_layer0<<<B, 256>>>(x, Wih0, Whh0, bih0, bhh0);
    lstm_layer1_fc<<<B, 256>>>(Wih1, Whh1, bih1, bhh1, fcW, fcb, out);
}

// round 3
// speedup vs baseline: 1.3994x; 1.3994x over previous
#include <cuda_runtime.h>
#include <cstdint>

#define T_STEPS 2048
#define HID 64
#define EPB 7          // batch elements per block  -> grid 147 = single wave

typedef unsigned long long u64;

// ---------- f32x2 packed math ----------
__device__ __forceinline__ u64 fma2(u64 a, u64 b, u64 c) {
    u64 d; asm("fma.rn.f32x2 %0, %1, %2, %3;" : "=l"(d) : "l"(a), "l"(b), "l"(c)); return d;
}
__device__ __forceinline__ u64 pack2(float lo, float hi) {
    u64 d; asm("mov.b64 %0, {%1, %2};" : "=l"(d) : "f"(lo), "f"(hi)); return d;
}
__device__ __forceinline__ float2 unpack2(u64 v) {
    float a, b; asm("mov.b64 {%0, %1}, %2;" : "=f"(a), "=f"(b) : "l"(v));
    return make_float2(a, b);
}

// ---------- activations ----------
__device__ __forceinline__ float sigmoid_(float x) {
    return __fdividef(1.0f, 1.0f + __expf(-x));
}
__device__ __forceinline__ float tanh_(float x) {
    float e = __expf(2.0f * fabsf(x));
    float t = 1.0f - __fdividef(2.0f, e + 1.0f);
    return copysignf(t, x);
}

__device__ __forceinline__ void cp_async16(void* sptr, const void* gptr) {
    uint32_t sa = (uint32_t)__cvta_generic_to_shared(sptr);
    asm volatile("cp.async.ca.shared.global [%0], [%1], 16;" :: "r"(sa), "l"(gptr));
}
#define CP_COMMIT() asm volatile("cp.async.commit_group;")
#define CP_WAIT0()  asm volatile("cp.async.wait_group 0;")

// 512 MB scratch for layer-0 hidden states
__device__ float g_h1[(size_t)1024 * T_STEPS * HID];

extern __shared__ char smem_raw[];

// =====================================================================================
// Layer 0. block = 256 thr = 64 units (t) x 4 k-splits (s); EPB elements per block.
// Thread (t,s): 4 gates of unit t, k in [16s,16s+16), k-pair packed f32x2 weights (64 regs).
// Phase 1: partial dot products for all EPB elements -> psh (float4 per gate-quad).
// Phase 2: group s reduces/activates elements {s, s+4}; writes h + g_h1.
// =====================================================================================
__global__ void __launch_bounds__(256, 1)
lstm_layer0(const float* __restrict__ x, const float* __restrict__ Wih0,
            const float* __restrict__ Whh0, const float* __restrict__ bih0,
            const float* __restrict__ bhh0, int B)
{
    float*  x_sh  = (float*)smem_raw;                               // [EPB][T_STEPS]  56 KB
    float*  h_sh  = (float*)(smem_raw + EPB * T_STEPS * 4);         // [2][EPB][HID]   3.5 KB
    float4* psh   = (float4*)(smem_raw + EPB * T_STEPS * 4 + 2 * EPB * HID * 4); // [4][EPB][HID] 28 KB

    const int tid = threadIdx.x;
    const int t = tid & 63;
    const int s = tid >> 6;
    const int b0 = blockIdx.x * EPB;

    // stage EPB input rows (coalesced float4)
    for (int i = tid; i < EPB * T_STEPS / 4; i += 256) {
        int e = i / (T_STEPS / 4), q = i % (T_STEPS / 4);
        int be = b0 + e; if (be > B - 1) be = B - 1;
        ((float4*)x_sh)[i] = ((const float4*)(x + (size_t)be * T_STEPS))[q];
    }

    // weights: k-pair packed per gate. w[g][p] = (W[g][k0+2p], W[g][k0+2p+1])
    u64 w[4][8];
    float xw[4], bs[4];
#pragma unroll
    for (int g = 0; g < 4; ++g) {
        const int r = g * 64 + t;
        const int k0 = s * 16;
#pragma unroll
        for (int p = 0; p < 8; ++p)
            w[g][p] = pack2(Whh0[r * 64 + k0 + 2 * p], Whh0[r * 64 + k0 + 2 * p + 1]);
        xw[g] = Wih0[r];
        bs[g] = bih0[r] + bhh0[r];
    }
    float c0 = 0.0f, c1 = 0.0f;

    for (int i = tid; i < EPB * HID; i += 256) h_sh[i] = 0.0f;  // h_sh[0][*][*] = 0
    __syncthreads();

#pragma unroll 1
    for (int step = 0; step < T_STEPS; ++step) {
        const int buf = step & 1;
        // ---- phase 1: partials for all elements ----
#pragma unroll 1
        for (int e = 0; e < EPB; ++e) {
            const ulonglong2* hp = (const ulonglong2*)&h_sh[(buf * EPB + e) * HID + s * 16];
            u64 a0 = 0, a1 = 0, a2 = 0, a3 = 0;
#pragma unroll
            for (int q = 0; q < 4; ++q) {
                ulonglong2 v = hp[q];
                a0 = fma2(v.x, w[0][2 * q], a0); a1 = fma2(v.x, w[1][2 * q], a1);
                a2 = fma2(v.x, w[2][2 * q], a2); a3 = fma2(v.x, w[3][2 * q], a3);
                a0 = fma2(v.y, w[0][2 * q + 1], a0); a1 = fma2(v.y, w[1][2 * q + 1], a1);
                a2 = fma2(v.y, w[2][2 * q + 1], a2); a3 = fma2(v.y, w[3][2 * q + 1], a3);
            }
            float2 p0 = unpack2(a0), p1 = unpack2(a1), p2 = unpack2(a2), p3 = unpack2(a3);
            psh[(s * EPB + e) * HID + t] =
                make_float4(p0.x + p0.y, p1.x + p1.y, p2.x + p2.y, p3.x + p3.y);
        }
        __syncthreads();
        // ---- phase 2: group s handles elements s and s+4 ----
        {
            const int e = s;
            float4 q0 = psh[(0 * EPB + e) * HID + t], q1 = psh[(1 * EPB + e) * HID + t];
            float4 q2 = psh[(2 * EPB + e) * HID + t], q3 = psh[(3 * EPB + e) * HID + t];
            float xv = x_sh[e * T_STEPS + step];
            float gi = sigmoid_(q0.x + q1.x + q2.x + q3.x + xv * xw[0] + bs[0]);
            float gf = sigmoid_(q0.y + q1.y + q2.y + q3.y + xv * xw[1] + bs[1]);
            float gg = tanh_   (q0.z + q1.z + q2.z + q3.z + xv * xw[2] + bs[2]);
            float go = sigmoid_(q0.w + q1.w + q2.w + q3.w + xv * xw[3] + bs[3]);
            c0 = gf * c0 + gi * gg;
            float h = go * tanh_(c0);
            h_sh[((buf ^ 1) * EPB + e) * HID + t] = h;
            int be = b0 + e; if (be > B - 1) be = B - 1;
            g_h1[((size_t)be * T_STEPS + step) * HID + t] = h;
        }
        if (s < 3) {
            const int e = s + 4;
            float4 q0 = psh[(0 * EPB + e) * HID + t], q1 = psh[(1 * EPB + e) * HID + t];
            float4 q2 = psh[(2 * EPB + e) * HID + t], q3 = psh[(3 * EPB + e) * HID + t];
            float xv = x_sh[e * T_STEPS + step];
            float gi = sigmoid_(q0.x + q1.x + q2.x + q3.x + xv * xw[0] + bs[0]);
            float gf = sigmoid_(q0.y + q1.y + q2.y + q3.y + xv * xw[1] + bs[1]);
            float gg = tanh_   (q0.z + q1.z + q2.z + q3.z + xv * xw[2] + bs[2]);
            float go = sigmoid_(q0.w + q1.w + q2.w + q3.w + xv * xw[3] + bs[3]);
            c1 = gf * c1 + gi * gg;
            float h = go * tanh_(c1);
            h_sh[((buf ^ 1) * EPB + e) * HID + t] = h;
            int be = b0 + e; if (be > B - 1) be = B - 1;
            g_h1[((size_t)be * T_STEPS + step) * HID + t] = h;
        }
        __syncthreads();
    }
}

// =====================================================================================
// Layer 1 + FC. Same structure, K = 128 (64 h1 streamed + 64 recurrent).
// s<2 threads consume the streamed h1 chunk, s>=2 threads consume recurrent h2.
// h1 streamed in 8-step chunks, cp.async double buffered.
// =====================================================================================
__global__ void __launch_bounds__(256, 1)
lstm_layer1_fc(const float* __restrict__ Wih1, const float* __restrict__ Whh1,
               const float* __restrict__ bih1, const float* __restrict__ bhh1,
               const float* __restrict__ fcW, const float* __restrict__ fcb,
               float* __restrict__ out, int B)
{
    float*  in1  = (float*)smem_raw;                                // [2][8][EPB][HID] 28 KB
    float*  h_sh = (float*)(smem_raw + 2 * 8 * EPB * HID * 4);      // [2][EPB][HID]
    float4* psh  = (float4*)(smem_raw + 2 * 8 * EPB * HID * 4 + 2 * EPB * HID * 4); // [4][EPB][HID]

    const int tid = threadIdx.x;
    const int t = tid & 63;
    const int s = tid >> 6;
    const int b0 = blockIdx.x * EPB;

    // weights: combined K=128; s<2 -> Wih1 rows, s>=2 -> Whh1 rows. 64 u64 = 128 regs.
    u64 w[4][16];
    float bs[4];
    {
        const float* Wsrc = (s < 2) ? Wih1 : Whh1;
        const int kb = (s < 2) ? s * 32 : (s - 2) * 32;
#pragma unroll
        for (int g = 0; g < 4; ++g) {
            const int r = g * 64 + t;
#pragma unroll
            for (int p = 0; p < 16; ++p)
                w[g][p] = pack2(Wsrc[r * 64 + kb + 2 * p], Wsrc[r * 64 + kb + 2 * p + 1]);
            bs[g] = bih1[r] + bhh1[r];
        }
    }
    float c0 = 0.0f, c1 = 0.0f;

    // element -> clamped batch row
    size_t rowbase[EPB];
#pragma unroll
    for (int e = 0; e < EPB; ++e) {
        int be = b0 + e; if (be > B - 1) be = B - 1;
        rowbase[e] = (size_t)be * T_STEPS;
    }

    // prologue: chunk 0 -> in1[0]
    for (int i = tid; i < 8 * EPB * 16; i += 256) {
        int st = i / (EPB * 16), rem = i % (EPB * 16);
        int e = rem / 16, q = rem % 16;
        cp_async16(&in1[((0 * 8 + st) * EPB + e) * HID + q * 4],
                   &g_h1[(rowbase[e] + st) * HID + q * 4]);
    }
    CP_COMMIT();
    for (int i = tid; i < EPB * HID; i += 256) h_sh[i] = 0.0f;
    CP_WAIT0();
    __syncthreads();

#pragma unroll 1
    for (int step = 0; step < T_STEPS; ++step) {
        const int buf = step & 1;
        const int cb = (step >> 3) & 1;
        const int st = step & 7;

        if ((step & 7) == 0) {   // prefetch next 8-step chunk into the other buffer
            int nc = (step >> 3) + 1;
            if (nc < T_STEPS / 8) {
                for (int i = tid; i < 8 * EPB * 16; i += 256) {
                    int cst = i / (EPB * 16), rem = i % (EPB * 16);
                    int e = rem / 16, q = rem % 16;
                    cp_async16(&in1[(((cb ^ 1) * 8 + cst) * EPB + e) * HID + q * 4],
                               &g_h1[(rowbase[e] + nc * 8 + cst) * HID + q * 4]);
                }
                CP_COMMIT();
            }
        }

        // ---- phase 1 ----
#pragma unroll 1
        for (int e = 0; e < EPB; ++e) {
            const ulonglong2* hp = (s < 2)
                ? (const ulonglong2*)&in1[((cb * 8 + st) * EPB + e) * HID + s * 32]
                : (const ulonglong2*)&h_sh[(buf * EPB + e) * HID + (s - 2) * 32];
            u64 a0 = 0, a1 = 0, a2 = 0, a3 = 0;
#pragma unroll
            for (int q = 0; q < 8; ++q) {
                ulonglong2 v = hp[q];
                a0 = fma2(v.x, w[0][2 * q], a0); a1 = fma2(v.x, w[1][2 * q], a1);
                a2 = fma2(v.x, w[2][2 * q], a2); a3 = fma2(v.x, w[3][2 * q], a3);
                a0 = fma2(v.y, w[0][2 * q + 1], a0); a1 = fma2(v.y, w[1][2 * q + 1], a1);
                a2 = fma2(v.y, w[2][2 * q + 1], a2); a3 = fma2(v.y, w[3][2 * q + 1], a3);
            }
            float2 p0 = unpack2(a0), p1 = unpack2(a1), p2 = unpack2(a2), p3 = unpack2(a3);
            psh[(s * EPB + e) * HID + t] =
                make_float4(p0.x + p0.y, p1.x + p1.y, p2.x + p2.y, p3.x + p3.y);
        }
        __syncthreads();
        // ---- phase 2 ----
        {
            const int e = s;
            float4 q0 = psh[(0 * EPB + e) * HID + t], q1 = psh[(1 * EPB + e) * HID + t];
            float4 q2 = psh[(2 * EPB + e) * HID + t], q3 = psh[(3 * EPB + e) * HID + t];
            float gi = sigmoid_(q0.x + q1.x + q2.x + q3.x + bs[0]);
            float gf = sigmoid_(q0.y + q1.y + q2.y + q3.y + bs[1]);
            float gg = tanh_   (q0.z + q1.z + q2.z + q3.z + bs[2]);
            float go = sigmoid_(q0.w + q1.w + q2.w + q3.w + bs[3]);
            c0 = gf * c0 + gi * gg;
            h_sh[((buf ^ 1) * EPB + e) * HID + t] = go * tanh_(c0);
        }
        if (s < 3) {
            const int e = s + 4;
            float4 q0 = psh[(0 * EPB + e) * HID + t], q1 = psh[(1 * EPB + e) * HID + t];
            float4 q2 = psh[(2 * EPB + e) * HID + t], q3 = psh[(3 * EPB + e) * HID + t];
            float gi = sigmoid_(q0.x + q1.x + q2.x + q3.x + bs[0]);
            float gf = sigmoid_(q0.y + q1.y + q2.y + q3.y + bs[1]);
            float gg = tanh_   (q0.z + q1.z + q2.z + q3.z + bs[2]);
            float go = sigmoid_(q0.w + q1.w + q2.w + q3.w + bs[3]);
            c1 = gf * c1 + gi * gg;
            h_sh[((buf ^ 1) * EPB + e) * HID + t] = go * tanh_(c1);
        }
        if ((step & 7) == 7) CP_WAIT0();
        __syncthreads();
    }

    // final FC (final h2 sits in h_sh[0][e][*] since last step had buf=1)
    if (tid < EPB) {
        const int e = tid;
        int be = b0 + e; if (be > B - 1) be = B - 1;
        float acc = fcb[0];
#pragma unroll
        for (int k = 0; k < HID; ++k) acc += h_sh[(0 * EPB + e) * HID + k] * fcW[k];
        out[be] = acc;
    }
}

extern "C" void kernel_launch(void* const* d_in, const int* in_sizes, int n_in,
                              void* d_out, int out_size)
{
    const float* x    = (const float*)d_in[0];
    const float* Wih0 = (const float*)d_in[1];
    const float* Whh0 = (const float*)d_in[2];
    const float* bih0 = (const float*)d_in[3];
    const float* bhh0 = (const float*)d_in[4];
    const float* Wih1 = (const float*)d_in[5];
    const float* Whh1 = (const float*)d_in[6];
    const float* bih1 = (const float*)d_in[7];
    const float* bhh1 = (const float*)d_in[8];
    const float* fcW  = (const float*)d_in[9];
    const float* fcb  = (const float*)d_in[10];
    float* out = (float*)d_out;

    int B = in_sizes[0] / T_STEPS;
    if (B > 1024) B = 1024;
    int blocks = (B + EPB - 1) / EPB;

    const int smem0 = EPB * T_STEPS * 4 + 2 * EPB * HID * 4 + 4 * EPB * HID * 16; // ~89.6 KB
    const int smem1 = 2 * 8 * EPB * HID * 4 + 2 * EPB * HID * 4 + 4 * EPB * HID * 16; // ~61 KB

    static bool attr_set = false;
    if (!attr_set) {
        cudaFuncSetAttribute(lstm_layer0, cudaFuncAttributeMaxDynamicSharedMemorySize, smem0);
        cudaFuncSetAttribute(lstm_layer1_fc, cudaFuncAttributeMaxDynamicSharedMemorySize, smem1);
        attr_set = true;
    }

    lstm_layer0<<<blocks, 256, smem0>>>(x, Wih0, Whh0, bih0, bhh0, B);
    lstm_layer1_fc<<<blocks, 256, smem1>>>(Wih1, Whh1, bih1, bhh1, fcW, fcb, out, B);
}